// round 5
// baseline (speedup 1.0000x reference)
#include <cuda_runtime.h>
#include <cstdint>

// PSRoIPool: x (4, 1029, 96, 96) fp32, rois (512,5) fp32 [b,x1,y1,x2,y2]
// out (512, 21, 7, 7) fp32. Flat out idx = k*1029 + r; input channel = r;
// bin row i = (r%49)/7, bin col j = r%7.
//
// KEY NUMERIC DETAIL: the JAX/XLA reference effectively computes
//   bin = roi_extent * fl(1/7)   (reciprocal multiply)
// not an IEEE division. For roi extents divisible by 7 this perturbs every
// ceil() bin end by +1 row/col. We replicate the reciprocal-multiply with
// explicit rn intrinsics so nvcc cannot re-fold it.

#define C_TOT   1029
#define PH      7
#define PW      7
#define HH      96
#define WW      96
#define PLANE   (HH*WW)
#define KROIS   512
#define SCALE   0.0625f
#define TOTAL   (KROIS * C_TOT)

// fl(1/7) in fp32 = 0x3E124925
#define RCP7    0.1428571492433547973632812500f

__global__ __launch_bounds__(256) void psroi_kernel(
    const float* __restrict__ x,
    const float* __restrict__ rois,
    float* __restrict__ out)
{
    int idx = blockIdx.x * blockDim.x + threadIdx.x;
    if (idx >= TOTAL) return;

    int k  = idx / C_TOT;
    int r  = idx - k * C_TOT;          // channel in x AND packed (c,i,j)
    int ij = r % (PH * PW);
    int i  = ij / PW;
    int j  = ij - i * PW;

    const float* roi = rois + k * 5;
    int b  = (int)roi[0];
    int sw = (int)floorf(__fmaf_rn(roi[1], SCALE, 0.5f));
    int sh = (int)floorf(__fmaf_rn(roi[2], SCALE, 0.5f));
    int ew = (int)floorf(__fmaf_rn(roi[3], SCALE, 0.5f));
    int eh = (int)floorf(__fmaf_rn(roi[4], SCALE, 0.5f));
    // (coord*2^-4 is exact, so fma vs mul+add are identical here.)

    float roi_w = (float)max(ew - sw, 1);
    float roi_h = (float)max(eh - sh, 1);

    // Reciprocal-multiply, matching XLA's div-by-constant lowering.
    float bin_h = __fmul_rn(roi_h, RCP7);
    float bin_w = __fmul_rn(roi_w, RCP7);

    int hstart = min(max((int)floorf(__fmul_rn((float)i,       bin_h)) + sh, 0), HH);
    int hend   = min(max((int)ceilf (__fmul_rn((float)(i + 1), bin_h)) + sh, 0), HH);
    int wstart = min(max((int)floorf(__fmul_rn((float)j,       bin_w)) + sw, 0), WW);
    int wend   = min(max((int)ceilf (__fmul_rn((float)(j + 1), bin_w)) + sw, 0), WW);

    int area = (hend - hstart) * (wend - wstart);

    float sum = 0.0f;
    if (area > 0) {
        const float* plane = x + ((size_t)b * C_TOT + r) * PLANE;
        for (int hy = hstart; hy < hend; ++hy) {
            const float* row = plane + hy * WW;
            float s = 0.0f;
            for (int wx = wstart; wx < wend; ++wx)
                s += __ldg(row + wx);
            sum += s;
        }
        sum = __fdiv_rn(sum, (float)area);
    }
    out[idx] = sum;   // always write (d_out is poisoned)
}

extern "C" void kernel_launch(void* const* d_in, const int* in_sizes, int n_in,
                              void* d_out, int out_size)
{
    // Bind by size: rois has KROIS*5 = 2560 elements.
    const float* x;
    const float* rois;
    if (n_in >= 2 && in_sizes[0] == KROIS * 5) {
        rois = (const float*)d_in[0];
        x    = (const float*)d_in[1];
    } else {
        x    = (const float*)d_in[0];
        rois = (const float*)d_in[1];
    }
    float* out = (float*)d_out;

    psroi_kernel<<<(TOTAL + 255) / 256, 256>>>(x, rois, out);
}